// round 1
// baseline (speedup 1.0000x reference)
#include <cuda_runtime.h>

#define DM   1024
#define SEQ  2048
#define BATCH 4
#define NH   16
#define DH   64

// Scratch (allocation-free): 4 x 32 MiB
__device__ float g_Q[BATCH * NH * SEQ * DH];   // [B,H,S,Dh], pre-scaled by Dh^-0.5
__device__ float g_K[BATCH * NH * SEQ * DH];   // [B,H,S,Dh]
__device__ float g_V[BATCH * NH * SEQ * DH];   // [B,H,S,Dh]
__device__ float g_O[BATCH * SEQ * DM];        // [B,S,D]

// ============================================================================
// GEMM C[m,n] = sum_k A[m,k] * W[n,k]   (A: MxK row-major, W: NxK row-major)
// 128x128 tile, K-step 16, 256 threads, 8x8 per-thread micro-tile.
// ============================================================================

__global__ __launch_bounds__(256) void qkv_gemm(const float* __restrict__ Xq,
                                                const float* __restrict__ Xkv,
                                                const float* __restrict__ Wq,
                                                const float* __restrict__ Wk,
                                                const float* __restrict__ Wv) {
    __shared__ __align__(16) float As[16][132];
    __shared__ __align__(16) float Bs[16][132];

    const int bz = blockIdx.z;
    const float* A   = (bz == 0) ? Xq : Xkv;
    const float* W   = (bz == 0) ? Wq : ((bz == 1) ? Wk : Wv);
    float*       out = (bz == 0) ? g_Q : ((bz == 1) ? g_K : g_V);
    const float scale = (bz == 0) ? 0.125f : 1.0f;   // 1/sqrt(64) folded into Q

    const int m0 = blockIdx.y * 128;
    const int n0 = blockIdx.x * 128;
    const int tid = threadIdx.x;
    const int tx = tid & 15, ty = tid >> 4;
    const int lr = tid >> 2;           // 0..63
    const int lc = (tid & 3) << 2;     // 0,4,8,12

    float acc[8][8];
#pragma unroll
    for (int i = 0; i < 8; i++)
#pragma unroll
        for (int j = 0; j < 8; j++) acc[i][j] = 0.0f;

    const float* Aptr = A + (size_t)(m0 + lr) * DM + lc;
    const float* Wptr = W + (size_t)(n0 + lr) * DM + lc;

    for (int kt = 0; kt < DM; kt += 16) {
        float4 a0 = *(const float4*)(Aptr + kt);
        float4 a1 = *(const float4*)(Aptr + (size_t)64 * DM + kt);
        float4 b0 = *(const float4*)(Wptr + kt);
        float4 b1 = *(const float4*)(Wptr + (size_t)64 * DM + kt);
        __syncthreads();
        As[lc + 0][lr] = a0.x; As[lc + 1][lr] = a0.y;
        As[lc + 2][lr] = a0.z; As[lc + 3][lr] = a0.w;
        As[lc + 0][lr + 64] = a1.x; As[lc + 1][lr + 64] = a1.y;
        As[lc + 2][lr + 64] = a1.z; As[lc + 3][lr + 64] = a1.w;
        Bs[lc + 0][lr] = b0.x; Bs[lc + 1][lr] = b0.y;
        Bs[lc + 2][lr] = b0.z; Bs[lc + 3][lr] = b0.w;
        Bs[lc + 0][lr + 64] = b1.x; Bs[lc + 1][lr + 64] = b1.y;
        Bs[lc + 2][lr + 64] = b1.z; Bs[lc + 3][lr + 64] = b1.w;
        __syncthreads();
#pragma unroll
        for (int k = 0; k < 16; k++) {
            float4 af0 = *(const float4*)&As[k][ty * 8];
            float4 af1 = *(const float4*)&As[k][ty * 8 + 4];
            float4 bf0 = *(const float4*)&Bs[k][tx * 8];
            float4 bf1 = *(const float4*)&Bs[k][tx * 8 + 4];
            float a[8] = {af0.x, af0.y, af0.z, af0.w, af1.x, af1.y, af1.z, af1.w};
            float b[8] = {bf0.x, bf0.y, bf0.z, bf0.w, bf1.x, bf1.y, bf1.z, bf1.w};
#pragma unroll
            for (int i = 0; i < 8; i++)
#pragma unroll
                for (int j = 0; j < 8; j++) acc[i][j] += a[i] * b[j];
        }
    }

    // Epilogue: write [B,H,S,Dh]
#pragma unroll
    for (int i = 0; i < 8; i++) {
        const int m = m0 + ty * 8 + i;
        const int b = m >> 11;          // S = 2048
        const int s = m & 2047;
#pragma unroll
        for (int j = 0; j < 8; j++) {
            const int n = n0 + tx * 8 + j;
            const int h = n >> 6;       // Dh = 64
            const int dh = n & 63;
            out[(((size_t)((b << 4) + h) * SEQ) + s) * DH + dh] = acc[i][j] * scale;
        }
    }
}

__global__ __launch_bounds__(256) void proj_gemm(const float* __restrict__ Wo,
                                                 float* __restrict__ C) {
    __shared__ __align__(16) float As[16][132];
    __shared__ __align__(16) float Bs[16][132];

    const int m0 = blockIdx.y * 128;
    const int n0 = blockIdx.x * 128;
    const int tid = threadIdx.x;
    const int tx = tid & 15, ty = tid >> 4;
    const int lr = tid >> 2;
    const int lc = (tid & 3) << 2;

    float acc[8][8];
#pragma unroll
    for (int i = 0; i < 8; i++)
#pragma unroll
        for (int j = 0; j < 8; j++) acc[i][j] = 0.0f;

    const float* Aptr = g_O + (size_t)(m0 + lr) * DM + lc;
    const float* Wptr = Wo + (size_t)(n0 + lr) * DM + lc;

    for (int kt = 0; kt < DM; kt += 16) {
        float4 a0 = *(const float4*)(Aptr + kt);
        float4 a1 = *(const float4*)(Aptr + (size_t)64 * DM + kt);
        float4 b0 = *(const float4*)(Wptr + kt);
        float4 b1 = *(const float4*)(Wptr + (size_t)64 * DM + kt);
        __syncthreads();
        As[lc + 0][lr] = a0.x; As[lc + 1][lr] = a0.y;
        As[lc + 2][lr] = a0.z; As[lc + 3][lr] = a0.w;
        As[lc + 0][lr + 64] = a1.x; As[lc + 1][lr + 64] = a1.y;
        As[lc + 2][lr + 64] = a1.z; As[lc + 3][lr + 64] = a1.w;
        Bs[lc + 0][lr] = b0.x; Bs[lc + 1][lr] = b0.y;
        Bs[lc + 2][lr] = b0.z; Bs[lc + 3][lr] = b0.w;
        Bs[lc + 0][lr + 64] = b1.x; Bs[lc + 1][lr + 64] = b1.y;
        Bs[lc + 2][lr + 64] = b1.z; Bs[lc + 3][lr + 64] = b1.w;
        __syncthreads();
#pragma unroll
        for (int k = 0; k < 16; k++) {
            float4 af0 = *(const float4*)&As[k][ty * 8];
            float4 af1 = *(const float4*)&As[k][ty * 8 + 4];
            float4 bf0 = *(const float4*)&Bs[k][tx * 8];
            float4 bf1 = *(const float4*)&Bs[k][tx * 8 + 4];
            float a[8] = {af0.x, af0.y, af0.z, af0.w, af1.x, af1.y, af1.z, af1.w};
            float b[8] = {bf0.x, bf0.y, bf0.z, bf0.w, bf1.x, bf1.y, bf1.z, bf1.w};
#pragma unroll
            for (int i = 0; i < 8; i++)
#pragma unroll
                for (int j = 0; j < 8; j++) acc[i][j] += a[i] * b[j];
        }
    }

#pragma unroll
    for (int i = 0; i < 8; i++) {
        const int m = m0 + ty * 8 + i;
        float4 w0 = make_float4(acc[i][0], acc[i][1], acc[i][2], acc[i][3]);
        float4 w1 = make_float4(acc[i][4], acc[i][5], acc[i][6], acc[i][7]);
        *(float4*)&C[(size_t)m * DM + n0 + tx * 8]     = w0;
        *(float4*)&C[(size_t)m * DM + n0 + tx * 8 + 4] = w1;
    }
}

// ============================================================================
// Flash attention (causal): Bq=Bk=64, Dh=64, 128 threads.
// smem: Qs[d][r], Ks[d][c] (transposed), Vs[c][d], Ps[c][r]; stride 68.
// ============================================================================

#define BQ 64
#define BK 64
#define SPAD 68
#define SM_Q 0
#define SM_K (64 * SPAD)
#define SM_V (2 * 64 * SPAD)
#define SM_P (3 * 64 * SPAD)
#define ATTN_SMEM_BYTES (4 * 64 * SPAD * 4)

__global__ __launch_bounds__(128) void attn_kernel() {
    extern __shared__ __align__(16) float sm[];
    const int tid = threadIdx.x;
    const int tx = tid & 15;        // 0..15 -> 4 cols each
    const int ty = tid >> 4;        // 0..7  -> 8 rows each
    const int qt = (int)(gridDim.x - 1) - (int)blockIdx.x;  // heavy tiles first
    const int bh = blockIdx.y;
    const int q0 = qt * BQ;
    const size_t base = (size_t)bh * SEQ * DH;

    // Load Q tile transposed: Qs[d][r]
    for (int i = tid; i < BQ * (DH / 4); i += 128) {
        const int r = i >> 4;
        const int c4 = (i & 15) << 2;
        float4 v = *(const float4*)&g_Q[base + (size_t)(q0 + r) * DH + c4];
        sm[SM_Q + (c4 + 0) * SPAD + r] = v.x;
        sm[SM_Q + (c4 + 1) * SPAD + r] = v.y;
        sm[SM_Q + (c4 + 2) * SPAD + r] = v.z;
        sm[SM_Q + (c4 + 3) * SPAD + r] = v.w;
    }

    float o[8][4];
    float mrow[8], lrow[8];
#pragma unroll
    for (int i = 0; i < 8; i++) {
        mrow[i] = -1e30f;
        lrow[i] = 0.0f;
#pragma unroll
        for (int j = 0; j < 4; j++) o[i][j] = 0.0f;
    }

    const int ntiles = qt + 1;
    for (int t = 0; t < ntiles; t++) {
        const int k0 = t * BK;
        __syncthreads();
        // Load K (transposed) and V tiles
        for (int i = tid; i < BK * (DH / 4); i += 128) {
            const int r = i >> 4;
            const int c4 = (i & 15) << 2;
            float4 kv = *(const float4*)&g_K[base + (size_t)(k0 + r) * DH + c4];
            sm[SM_K + (c4 + 0) * SPAD + r] = kv.x;
            sm[SM_K + (c4 + 1) * SPAD + r] = kv.y;
            sm[SM_K + (c4 + 2) * SPAD + r] = kv.z;
            sm[SM_K + (c4 + 3) * SPAD + r] = kv.w;
            float4 vv = *(const float4*)&g_V[base + (size_t)(k0 + r) * DH + c4];
            *(float4*)&sm[SM_V + r * SPAD + c4] = vv;
        }
        __syncthreads();

        // Scores S = Q . K  (Q pre-scaled)
        float s[8][4];
#pragma unroll
        for (int i = 0; i < 8; i++)
#pragma unroll
            for (int j = 0; j < 4; j++) s[i][j] = 0.0f;

#pragma unroll 8
        for (int d = 0; d < DH; d++) {
            float4 q0v = *(const float4*)&sm[SM_Q + d * SPAD + ty * 8];
            float4 q1v = *(const float4*)&sm[SM_Q + d * SPAD + ty * 8 + 4];
            float4 kv  = *(const float4*)&sm[SM_K + d * SPAD + tx * 4];
            float qa[8] = {q0v.x, q0v.y, q0v.z, q0v.w, q1v.x, q1v.y, q1v.z, q1v.w};
            float kb[4] = {kv.x, kv.y, kv.z, kv.w};
#pragma unroll
            for (int i = 0; i < 8; i++)
#pragma unroll
                for (int j = 0; j < 4; j++) s[i][j] += qa[i] * kb[j];
        }

        // Causal mask only on the diagonal tile
        if (k0 == q0) {
#pragma unroll
            for (int i = 0; i < 8; i++)
#pragma unroll
                for (int j = 0; j < 4; j++)
                    if (tx * 4 + j > ty * 8 + i) s[i][j] = -1e30f;
        }

        // Online softmax update
#pragma unroll
        for (int i = 0; i < 8; i++) {
            float mx = fmaxf(fmaxf(s[i][0], s[i][1]), fmaxf(s[i][2], s[i][3]));
#pragma unroll
            for (int off = 8; off > 0; off >>= 1)
                mx = fmaxf(mx, __shfl_xor_sync(0xffffffffu, mx, off));
            const float mnew = fmaxf(mrow[i], mx);
            const float alpha = __expf(mrow[i] - mnew);
            float rs = 0.0f;
#pragma unroll
            for (int j = 0; j < 4; j++) {
                const float p = __expf(s[i][j] - mnew);
                rs += p;
                sm[SM_P + (tx * 4 + j) * SPAD + ty * 8 + i] = p;
            }
#pragma unroll
            for (int off = 8; off > 0; off >>= 1)
                rs += __shfl_xor_sync(0xffffffffu, rs, off);
            lrow[i] = lrow[i] * alpha + rs;
            mrow[i] = mnew;
#pragma unroll
            for (int j = 0; j < 4; j++) o[i][j] *= alpha;
        }
        __syncthreads();

        // O += P @ V
#pragma unroll 8
        for (int c = 0; c < BK; c++) {
            float4 p0 = *(const float4*)&sm[SM_P + c * SPAD + ty * 8];
            float4 p1 = *(const float4*)&sm[SM_P + c * SPAD + ty * 8 + 4];
            float4 vv = *(const float4*)&sm[SM_V + c * SPAD + tx * 4];
            float pa[8] = {p0.x, p0.y, p0.z, p0.w, p1.x, p1.y, p1.z, p1.w};
            float vb[4] = {vv.x, vv.y, vv.z, vv.w};
#pragma unroll
            for (int i = 0; i < 8; i++)
#pragma unroll
                for (int j = 0; j < 4; j++) o[i][j] += pa[i] * vb[j];
        }
    }

    // Normalize and write to [B,S,D]
    const int b = bh >> 4, h = bh & 15;
#pragma unroll
    for (int i = 0; i < 8; i++) {
        const float inv = 1.0f / lrow[i];
        const int row = q0 + ty * 8 + i;
        float4 w = make_float4(o[i][0] * inv, o[i][1] * inv, o[i][2] * inv, o[i][3] * inv);
        *(float4*)&g_O[((size_t)(b * SEQ + row)) * DM + h * DH + tx * 4] = w;
    }
}

// ============================================================================
// Launch
// ============================================================================

extern "C" void kernel_launch(void* const* d_in, const int* in_sizes, int n_in,
                              void* d_out, int out_size) {
    const float* q  = (const float*)d_in[0];
    const float* kv = (const float*)d_in[1];
    const float* Wq = (const float*)d_in[2];
    const float* Wk = (const float*)d_in[3];
    const float* Wv = (const float*)d_in[4];
    const float* Wo = (const float*)d_in[5];
    float* out = (float*)d_out;

    cudaFuncSetAttribute(attn_kernel, cudaFuncAttributeMaxDynamicSharedMemorySize,
                         ATTN_SMEM_BYTES);

    // 1) QKV projections (z: 0=Q,1=K,2=V) -> [B,H,S,Dh] scratch, Q pre-scaled
    qkv_gemm<<<dim3(DM / 128, (BATCH * SEQ) / 128, 3), 256>>>(q, kv, Wq, Wk, Wv);

    // 2) Causal flash attention -> g_O [B,S,D]
    attn_kernel<<<dim3(SEQ / BQ, BATCH * NH), 128, ATTN_SMEM_BYTES>>>();

    // 3) Output projection -> d_out
    proj_gemm<<<dim3(DM / 128, (BATCH * SEQ) / 128), 256>>>(Wo, out);
}

// round 3
// speedup vs baseline: 1.5546x; 1.5546x over previous
#include <cuda_runtime.h>
#include <cstdint>

#define DM   1024
#define SEQ  2048
#define BATCH 4
#define NH   16
#define DH   64

// Scratch (allocation-free)
__device__ float g_Q[BATCH * NH * SEQ * DH];   // [B,H,S,Dh], pre-scaled by Dh^-0.5
__device__ float g_K[BATCH * NH * SEQ * DH];
__device__ float g_V[BATCH * NH * SEQ * DH];
__device__ float g_O[BATCH * SEQ * DM];        // [B,S,D]

// ============================================================================
// tf32 mma.sync helpers (plain sm_103-compatible; tcgen05 is rejected by the
// harness's compute_103 PTX stage, so we use the HMMA fallback path).
// ============================================================================
__device__ __forceinline__ uint32_t f2tf32(float x) {
    uint32_t u;
    asm("cvt.rna.tf32.f32 %0, %1;" : "=r"(u) : "f"(x));
    return u;
}

#define MMA_TF32(d, a, b0v, b1v)                                               \
    asm volatile("mma.sync.aligned.m16n8k8.row.col.f32.tf32.tf32.f32 "         \
                 "{%0,%1,%2,%3}, {%4,%5,%6,%7}, {%8,%9}, {%0,%1,%2,%3};"       \
                 : "+f"((d)[0]), "+f"((d)[1]), "+f"((d)[2]), "+f"((d)[3])      \
                 : "r"((a)[0]), "r"((a)[1]), "r"((a)[2]), "r"((a)[3]),         \
                   "r"(b0v), "r"(b1v))

// SMEM tile: 128 rows x 16 k-cols, row stride 20 words (conflict-free for
// fragment reads: banks (row*20 + col) % 32 all distinct over a warp).
#define SST 20

// ============================================================================
// C[m,n] = sum_k A[m,k] * W[n,k]; 128x128 CTA tile, 8 warps, warp tile 32x64.
// Double-buffered SMEM, register-staged gmem prefetch, 1 sync per K-step(16).
// acc fragment: acc[mt][nt][0..3]; epilogue emitted by caller via macro.
// ============================================================================
struct GemmFrag {
    float acc[2][8][4];
    int wm, wn, r, cl;
};

__device__ __forceinline__ void gemm_mainloop_mma(const float* __restrict__ Ablk,
                                                  const float* __restrict__ Wblk,
                                                  uint32_t (*As)[2560],
                                                  uint32_t (*Ws)[2560],
                                                  GemmFrag& fg, int tid) {
    const int wid = tid >> 5, lane = tid & 31;
    fg.wm = (wid & 3) * 32;
    fg.wn = (wid >> 2) * 64;
    fg.r = lane >> 2;
    fg.cl = lane & 3;
#pragma unroll
    for (int mt = 0; mt < 2; mt++)
#pragma unroll
        for (int nt = 0; nt < 8; nt++)
#pragma unroll
            for (int i = 0; i < 4; i++) fg.acc[mt][nt][i] = 0.0f;

    // prologue: load chunk 0
#pragma unroll
    for (int it = 0; it < 2; it++) {
        const int id = it * 256 + tid;
        const int row = id >> 2, f4 = id & 3;
        float4 va = *(const float4*)(Ablk + (size_t)row * DM + f4 * 4);
        float4 vw = *(const float4*)(Wblk + (size_t)row * DM + f4 * 4);
        uint4 ta = make_uint4(f2tf32(va.x), f2tf32(va.y), f2tf32(va.z), f2tf32(va.w));
        uint4 tw = make_uint4(f2tf32(vw.x), f2tf32(vw.y), f2tf32(vw.z), f2tf32(vw.w));
        *(uint4*)(&As[0][row * SST + f4 * 4]) = ta;
        *(uint4*)(&Ws[0][row * SST + f4 * 4]) = tw;
    }
    __syncthreads();

    float4 ra[2], rw[2];
#pragma unroll 1
    for (int c = 0; c < 64; c++) {
        const int cur = c & 1;
        if (c + 1 < 64) {
#pragma unroll
            for (int it = 0; it < 2; it++) {
                const int id = it * 256 + tid;
                const int row = id >> 2, f4 = id & 3;
                ra[it] = *(const float4*)(Ablk + (size_t)row * DM + (c + 1) * 16 + f4 * 4);
                rw[it] = *(const float4*)(Wblk + (size_t)row * DM + (c + 1) * 16 + f4 * 4);
            }
        }
        const uint32_t* as = As[cur];
        const uint32_t* ws = Ws[cur];
#pragma unroll
        for (int k0 = 0; k0 < 16; k0 += 8) {
            uint32_t af[2][4];
#pragma unroll
            for (int mt = 0; mt < 2; mt++) {
                const uint32_t* base = as + (fg.wm + mt * 16 + fg.r) * SST + k0 + fg.cl;
                af[mt][0] = base[0];
                af[mt][1] = base[8 * SST];
                af[mt][2] = base[4];
                af[mt][3] = base[8 * SST + 4];
            }
#pragma unroll
            for (int nt = 0; nt < 8; nt++) {
                const uint32_t* bb = ws + (fg.wn + nt * 8 + fg.r) * SST + k0 + fg.cl;
                const uint32_t b0 = bb[0], b1 = bb[4];
                MMA_TF32(fg.acc[0][nt], af[0], b0, b1);
                MMA_TF32(fg.acc[1][nt], af[1], b0, b1);
            }
        }
        if (c + 1 < 64) {
            const int nxt = cur ^ 1;
#pragma unroll
            for (int it = 0; it < 2; it++) {
                const int id = it * 256 + tid;
                const int row = id >> 2, f4 = id & 3;
                uint4 ta = make_uint4(f2tf32(ra[it].x), f2tf32(ra[it].y),
                                      f2tf32(ra[it].z), f2tf32(ra[it].w));
                uint4 tw = make_uint4(f2tf32(rw[it].x), f2tf32(rw[it].y),
                                      f2tf32(rw[it].z), f2tf32(rw[it].w));
                *(uint4*)(&As[nxt][row * SST + f4 * 4]) = ta;
                *(uint4*)(&Ws[nxt][row * SST + f4 * 4]) = tw;
            }
            __syncthreads();
        }
    }
}

// ============================================================================
// QKV projection: X[8192,1024] @ W[1024,1024]^T -> [B,H,S,Dh] (Q pre-scaled)
// ============================================================================
__global__ void __launch_bounds__(256) qkv_gemm_mma(const float* __restrict__ Xq,
                                                    const float* __restrict__ Xkv,
                                                    const float* __restrict__ Wq,
                                                    const float* __restrict__ Wk,
                                                    const float* __restrict__ Wv) {
    __shared__ uint32_t As[2][2560];
    __shared__ uint32_t Ws[2][2560];
    const int bz = blockIdx.z;
    const float* A = (bz == 0) ? Xq : Xkv;
    const float* W = (bz == 0) ? Wq : ((bz == 1) ? Wk : Wv);
    float* out     = (bz == 0) ? g_Q : ((bz == 1) ? g_K : g_V);
    const float scale = (bz == 0) ? 0.125f : 1.0f;

    const int m0 = blockIdx.y * 128;
    const int n0 = blockIdx.x * 128;
    const int tid = threadIdx.x;

    GemmFrag fg;
    gemm_mainloop_mma(A + (size_t)m0 * DM, W + (size_t)n0 * DM, As, Ws, fg, tid);

    // Epilogue: scatter to [B,H,S,Dh]
#pragma unroll
    for (int mt = 0; mt < 2; mt++) {
#pragma unroll
        for (int nt = 0; nt < 8; nt++) {
            const int mr = m0 + fg.wm + mt * 16 + fg.r;
            const int nc = n0 + fg.wn + nt * 8 + 2 * fg.cl;
            const int b = mr >> 11, s = mr & 2047;
            const int h = nc >> 6, dh = nc & 63;
            float* p0 = out + (((size_t)(b * NH + h) * SEQ + s) * DH + dh);
            *(float2*)p0 = make_float2(fg.acc[mt][nt][0] * scale, fg.acc[mt][nt][1] * scale);
            float* p1 = out + (((size_t)(b * NH + h) * SEQ + (s + 8)) * DH + dh);
            *(float2*)p1 = make_float2(fg.acc[mt][nt][2] * scale, fg.acc[mt][nt][3] * scale);
        }
    }
}

// ============================================================================
// Output projection: g_O[8192,1024] @ Wo[1024,1024]^T -> d_out
// ============================================================================
__global__ void __launch_bounds__(256) proj_gemm_mma(const float* __restrict__ Wo,
                                                     float* __restrict__ C) {
    __shared__ uint32_t As[2][2560];
    __shared__ uint32_t Ws[2][2560];
    const int m0 = blockIdx.y * 128;
    const int n0 = blockIdx.x * 128;
    const int tid = threadIdx.x;

    GemmFrag fg;
    gemm_mainloop_mma(g_O + (size_t)m0 * DM, Wo + (size_t)n0 * DM, As, Ws, fg, tid);

#pragma unroll
    for (int mt = 0; mt < 2; mt++) {
#pragma unroll
        for (int nt = 0; nt < 8; nt++) {
            const int mr = m0 + fg.wm + mt * 16 + fg.r;
            const int nc = n0 + fg.wn + nt * 8 + 2 * fg.cl;
            *(float2*)&C[(size_t)mr * DM + nc] =
                make_float2(fg.acc[mt][nt][0], fg.acc[mt][nt][1]);
            *(float2*)&C[(size_t)(mr + 8) * DM + nc] =
                make_float2(fg.acc[mt][nt][2], fg.acc[mt][nt][3]);
        }
    }
}

// ============================================================================
// Flash attention (causal, fp32): Bq=Bk=64, Dh=64, 128 threads. (unchanged)
// ============================================================================
#define BQ 64
#define BK 64
#define SPAD 68
#define SM_Q 0
#define SM_K (64 * SPAD)
#define SM_V (2 * 64 * SPAD)
#define SM_P (3 * 64 * SPAD)
#define ATTN_SMEM_BYTES (4 * 64 * SPAD * 4)

__global__ void __launch_bounds__(128) attn_kernel() {
    extern __shared__ __align__(16) float smf[];
    const int tid = threadIdx.x;
    const int tx = tid & 15;
    const int ty = tid >> 4;
    const int qt = (int)(gridDim.x - 1) - (int)blockIdx.x;
    const int bh = blockIdx.y;
    const int q0 = qt * BQ;
    const size_t base = (size_t)bh * SEQ * DH;

    for (int i = tid; i < BQ * (DH / 4); i += 128) {
        const int r = i >> 4;
        const int c4 = (i & 15) << 2;
        float4 v = *(const float4*)&g_Q[base + (size_t)(q0 + r) * DH + c4];
        smf[SM_Q + (c4 + 0) * SPAD + r] = v.x;
        smf[SM_Q + (c4 + 1) * SPAD + r] = v.y;
        smf[SM_Q + (c4 + 2) * SPAD + r] = v.z;
        smf[SM_Q + (c4 + 3) * SPAD + r] = v.w;
    }

    float o[8][4];
    float mrow[8], lrow[8];
#pragma unroll
    for (int i = 0; i < 8; i++) {
        mrow[i] = -1e30f;
        lrow[i] = 0.0f;
#pragma unroll
        for (int j = 0; j < 4; j++) o[i][j] = 0.0f;
    }

    const int ntiles = qt + 1;
    for (int t = 0; t < ntiles; t++) {
        const int k0 = t * BK;
        __syncthreads();
        for (int i = tid; i < BK * (DH / 4); i += 128) {
            const int r = i >> 4;
            const int c4 = (i & 15) << 2;
            float4 kv = *(const float4*)&g_K[base + (size_t)(k0 + r) * DH + c4];
            smf[SM_K + (c4 + 0) * SPAD + r] = kv.x;
            smf[SM_K + (c4 + 1) * SPAD + r] = kv.y;
            smf[SM_K + (c4 + 2) * SPAD + r] = kv.z;
            smf[SM_K + (c4 + 3) * SPAD + r] = kv.w;
            float4 vv = *(const float4*)&g_V[base + (size_t)(k0 + r) * DH + c4];
            *(float4*)&smf[SM_V + r * SPAD + c4] = vv;
        }
        __syncthreads();

        float s[8][4];
#pragma unroll
        for (int i = 0; i < 8; i++)
#pragma unroll
            for (int j = 0; j < 4; j++) s[i][j] = 0.0f;

#pragma unroll 8
        for (int d = 0; d < DH; d++) {
            float4 q0v = *(const float4*)&smf[SM_Q + d * SPAD + ty * 8];
            float4 q1v = *(const float4*)&smf[SM_Q + d * SPAD + ty * 8 + 4];
            float4 kv  = *(const float4*)&smf[SM_K + d * SPAD + tx * 4];
            float qa[8] = {q0v.x, q0v.y, q0v.z, q0v.w, q1v.x, q1v.y, q1v.z, q1v.w};
            float kb[4] = {kv.x, kv.y, kv.z, kv.w};
#pragma unroll
            for (int i = 0; i < 8; i++)
#pragma unroll
                for (int j = 0; j < 4; j++) s[i][j] += qa[i] * kb[j];
        }

        if (k0 == q0) {
#pragma unroll
            for (int i = 0; i < 8; i++)
#pragma unroll
                for (int j = 0; j < 4; j++)
                    if (tx * 4 + j > ty * 8 + i) s[i][j] = -1e30f;
        }

#pragma unroll
        for (int i = 0; i < 8; i++) {
            float mx = fmaxf(fmaxf(s[i][0], s[i][1]), fmaxf(s[i][2], s[i][3]));
#pragma unroll
            for (int off = 8; off > 0; off >>= 1)
                mx = fmaxf(mx, __shfl_xor_sync(0xffffffffu, mx, off));
            const float mnew = fmaxf(mrow[i], mx);
            const float alpha = __expf(mrow[i] - mnew);
            float rs = 0.0f;
#pragma unroll
            for (int j = 0; j < 4; j++) {
                const float p = __expf(s[i][j] - mnew);
                rs += p;
                smf[SM_P + (tx * 4 + j) * SPAD + ty * 8 + i] = p;
            }
#pragma unroll
            for (int off = 8; off > 0; off >>= 1)
                rs += __shfl_xor_sync(0xffffffffu, rs, off);
            lrow[i] = lrow[i] * alpha + rs;
            mrow[i] = mnew;
#pragma unroll
            for (int j = 0; j < 4; j++) o[i][j] *= alpha;
        }
        __syncthreads();

#pragma unroll 8
        for (int c = 0; c < BK; c++) {
            float4 p0 = *(const float4*)&smf[SM_P + c * SPAD + ty * 8];
            float4 p1 = *(const float4*)&smf[SM_P + c * SPAD + ty * 8 + 4];
            float4 vv = *(const float4*)&smf[SM_V + c * SPAD + tx * 4];
            float pa[8] = {p0.x, p0.y, p0.z, p0.w, p1.x, p1.y, p1.z, p1.w};
            float vb[4] = {vv.x, vv.y, vv.z, vv.w};
#pragma unroll
            for (int i = 0; i < 8; i++)
#pragma unroll
                for (int j = 0; j < 4; j++) o[i][j] += pa[i] * vb[j];
        }
    }

    const int b = bh >> 4, h = bh & 15;
#pragma unroll
    for (int i = 0; i < 8; i++) {
        const float inv = 1.0f / lrow[i];
        const int row = q0 + ty * 8 + i;
        float4 w = make_float4(o[i][0] * inv, o[i][1] * inv, o[i][2] * inv, o[i][3] * inv);
        *(float4*)&g_O[((size_t)(b * SEQ + row)) * DM + h * DH + tx * 4] = w;
    }
}

// ============================================================================
// Launch
// ============================================================================
extern "C" void kernel_launch(void* const* d_in, const int* in_sizes, int n_in,
                              void* d_out, int out_size) {
    const float* q  = (const float*)d_in[0];
    const float* kv = (const float*)d_in[1];
    const float* Wq = (const float*)d_in[2];
    const float* Wk = (const float*)d_in[3];
    const float* Wv = (const float*)d_in[4];
    const float* Wo = (const float*)d_in[5];
    float* out = (float*)d_out;

    cudaFuncSetAttribute(attn_kernel, cudaFuncAttributeMaxDynamicSharedMemorySize,
                         ATTN_SMEM_BYTES);

    qkv_gemm_mma<<<dim3(DM / 128, (BATCH * SEQ) / 128, 3), 256>>>(q, kv, Wq, Wk, Wv);
    attn_kernel<<<dim3(SEQ / BQ, BATCH * NH), 128, ATTN_SMEM_BYTES>>>();
    proj_gemm_mma<<<dim3(DM / 128, (BATCH * SEQ) / 128), 256>>>(Wo, out);
}

// round 4
// speedup vs baseline: 2.5452x; 1.6372x over previous
#include <cuda_runtime.h>
#include <cstdint>

#define DM   1024
#define SEQ  2048
#define BATCH 4
#define NH   16
#define DH   64

// Scratch (allocation-free)
__device__ float g_Q[BATCH * NH * SEQ * DH];   // [B,H,S,Dh], pre-scaled by Dh^-0.5
__device__ float g_K[BATCH * NH * SEQ * DH];
__device__ float g_V[BATCH * NH * SEQ * DH];
__device__ float g_O[BATCH * SEQ * DM];        // [B,S,D]

// ============================================================================
// tf32 mma.sync helpers
// ============================================================================
__device__ __forceinline__ uint32_t f2tf32(float x) {
    uint32_t u;
    asm("cvt.rna.tf32.f32 %0, %1;" : "=r"(u) : "f"(x));
    return u;
}

#define MMA_TF32(d, a, b0v, b1v)                                               \
    asm volatile("mma.sync.aligned.m16n8k8.row.col.f32.tf32.tf32.f32 "         \
                 "{%0,%1,%2,%3}, {%4,%5,%6,%7}, {%8,%9}, {%0,%1,%2,%3};"       \
                 : "+f"((d)[0]), "+f"((d)[1]), "+f"((d)[2]), "+f"((d)[3])      \
                 : "r"((a)[0]), "r"((a)[1]), "r"((a)[2]), "r"((a)[3]),         \
                   "r"(b0v), "r"(b1v))

#define SST 20

// ============================================================================
// GEMM mainloop (unchanged from round 3): 128x128 CTA tile, 8 warps.
// ============================================================================
struct GemmFrag {
    float acc[2][8][4];
    int wm, wn, r, cl;
};

__device__ __forceinline__ void gemm_mainloop_mma(const float* __restrict__ Ablk,
                                                  const float* __restrict__ Wblk,
                                                  uint32_t (*As)[2560],
                                                  uint32_t (*Ws)[2560],
                                                  GemmFrag& fg, int tid) {
    const int wid = tid >> 5, lane = tid & 31;
    fg.wm = (wid & 3) * 32;
    fg.wn = (wid >> 2) * 64;
    fg.r = lane >> 2;
    fg.cl = lane & 3;
#pragma unroll
    for (int mt = 0; mt < 2; mt++)
#pragma unroll
        for (int nt = 0; nt < 8; nt++)
#pragma unroll
            for (int i = 0; i < 4; i++) fg.acc[mt][nt][i] = 0.0f;

#pragma unroll
    for (int it = 0; it < 2; it++) {
        const int id = it * 256 + tid;
        const int row = id >> 2, f4 = id & 3;
        float4 va = *(const float4*)(Ablk + (size_t)row * DM + f4 * 4);
        float4 vw = *(const float4*)(Wblk + (size_t)row * DM + f4 * 4);
        uint4 ta = make_uint4(f2tf32(va.x), f2tf32(va.y), f2tf32(va.z), f2tf32(va.w));
        uint4 tw = make_uint4(f2tf32(vw.x), f2tf32(vw.y), f2tf32(vw.z), f2tf32(vw.w));
        *(uint4*)(&As[0][row * SST + f4 * 4]) = ta;
        *(uint4*)(&Ws[0][row * SST + f4 * 4]) = tw;
    }
    __syncthreads();

    float4 ra[2], rw[2];
#pragma unroll 1
    for (int c = 0; c < 64; c++) {
        const int cur = c & 1;
        if (c + 1 < 64) {
#pragma unroll
            for (int it = 0; it < 2; it++) {
                const int id = it * 256 + tid;
                const int row = id >> 2, f4 = id & 3;
                ra[it] = *(const float4*)(Ablk + (size_t)row * DM + (c + 1) * 16 + f4 * 4);
                rw[it] = *(const float4*)(Wblk + (size_t)row * DM + (c + 1) * 16 + f4 * 4);
            }
        }
        const uint32_t* as = As[cur];
        const uint32_t* ws = Ws[cur];
#pragma unroll
        for (int k0 = 0; k0 < 16; k0 += 8) {
            uint32_t af[2][4];
#pragma unroll
            for (int mt = 0; mt < 2; mt++) {
                const uint32_t* base = as + (fg.wm + mt * 16 + fg.r) * SST + k0 + fg.cl;
                af[mt][0] = base[0];
                af[mt][1] = base[8 * SST];
                af[mt][2] = base[4];
                af[mt][3] = base[8 * SST + 4];
            }
#pragma unroll
            for (int nt = 0; nt < 8; nt++) {
                const uint32_t* bb = ws + (fg.wn + nt * 8 + fg.r) * SST + k0 + fg.cl;
                const uint32_t b0 = bb[0], b1 = bb[4];
                MMA_TF32(fg.acc[0][nt], af[0], b0, b1);
                MMA_TF32(fg.acc[1][nt], af[1], b0, b1);
            }
        }
        if (c + 1 < 64) {
            const int nxt = cur ^ 1;
#pragma unroll
            for (int it = 0; it < 2; it++) {
                const int id = it * 256 + tid;
                const int row = id >> 2, f4 = id & 3;
                uint4 ta = make_uint4(f2tf32(ra[it].x), f2tf32(ra[it].y),
                                      f2tf32(ra[it].z), f2tf32(ra[it].w));
                uint4 tw = make_uint4(f2tf32(rw[it].x), f2tf32(rw[it].y),
                                      f2tf32(rw[it].z), f2tf32(rw[it].w));
                *(uint4*)(&As[nxt][row * SST + f4 * 4]) = ta;
                *(uint4*)(&Ws[nxt][row * SST + f4 * 4]) = tw;
            }
            __syncthreads();
        }
    }
}

__global__ void __launch_bounds__(256) qkv_gemm_mma(const float* __restrict__ Xq,
                                                    const float* __restrict__ Xkv,
                                                    const float* __restrict__ Wq,
                                                    const float* __restrict__ Wk,
                                                    const float* __restrict__ Wv) {
    __shared__ uint32_t As[2][2560];
    __shared__ uint32_t Ws[2][2560];
    const int bz = blockIdx.z;
    const float* A = (bz == 0) ? Xq : Xkv;
    const float* W = (bz == 0) ? Wq : ((bz == 1) ? Wk : Wv);
    float* out     = (bz == 0) ? g_Q : ((bz == 1) ? g_K : g_V);
    const float scale = (bz == 0) ? 0.125f : 1.0f;

    const int m0 = blockIdx.y * 128;
    const int n0 = blockIdx.x * 128;
    const int tid = threadIdx.x;

    GemmFrag fg;
    gemm_mainloop_mma(A + (size_t)m0 * DM, W + (size_t)n0 * DM, As, Ws, fg, tid);

#pragma unroll
    for (int mt = 0; mt < 2; mt++) {
#pragma unroll
        for (int nt = 0; nt < 8; nt++) {
            const int mr = m0 + fg.wm + mt * 16 + fg.r;
            const int nc = n0 + fg.wn + nt * 8 + 2 * fg.cl;
            const int b = mr >> 11, s = mr & 2047;
            const int h = nc >> 6, dh = nc & 63;
            float* p0 = out + (((size_t)(b * NH + h) * SEQ + s) * DH + dh);
            *(float2*)p0 = make_float2(fg.acc[mt][nt][0] * scale, fg.acc[mt][nt][1] * scale);
            float* p1 = out + (((size_t)(b * NH + h) * SEQ + (s + 8)) * DH + dh);
            *(float2*)p1 = make_float2(fg.acc[mt][nt][2] * scale, fg.acc[mt][nt][3] * scale);
        }
    }
}

__global__ void __launch_bounds__(256) proj_gemm_mma(const float* __restrict__ Wo,
                                                     float* __restrict__ C) {
    __shared__ uint32_t As[2][2560];
    __shared__ uint32_t Ws[2][2560];
    const int m0 = blockIdx.y * 128;
    const int n0 = blockIdx.x * 128;
    const int tid = threadIdx.x;

    GemmFrag fg;
    gemm_mainloop_mma(g_O + (size_t)m0 * DM, Wo + (size_t)n0 * DM, As, Ws, fg, tid);

#pragma unroll
    for (int mt = 0; mt < 2; mt++) {
#pragma unroll
        for (int nt = 0; nt < 8; nt++) {
            const int mr = m0 + fg.wm + mt * 16 + fg.r;
            const int nc = n0 + fg.wn + nt * 8 + 2 * fg.cl;
            *(float2*)&C[(size_t)mr * DM + nc] =
                make_float2(fg.acc[mt][nt][0], fg.acc[mt][nt][1]);
            *(float2*)&C[(size_t)(mr + 8) * DM + nc] =
                make_float2(fg.acc[mt][nt][2], fg.acc[mt][nt][3]);
        }
    }
}

// ============================================================================
// Flash attention with tf32 mma.sync.
// BQ=128, BK=64, Dh=64, 256 threads (8 warps x 16 q-rows each).
// smem (u32 words, stride 68): Qs[128x68] Ks[64x68] Vs(Vt)[64x68] Ps[128x68]
// ============================================================================
#define AST 68
#define OFF_Q 0
#define OFF_K (128 * AST)
#define OFF_V (192 * AST)
#define OFF_P (256 * AST)
#define ATTN_SMEM_BYTES (384 * AST * 4)

__global__ void __launch_bounds__(256) attn_mma() {
    extern __shared__ uint32_t sm4[];
    uint32_t* Qs = sm4 + OFF_Q;
    uint32_t* Ks = sm4 + OFF_K;
    uint32_t* Vs = sm4 + OFF_V;
    uint32_t* Ps = sm4 + OFF_P;

    const int tid = threadIdx.x;
    const int wid = tid >> 5, lane = tid & 31;
    const int r = lane >> 2, cl = lane & 3;
    const int qt = (int)(gridDim.x - 1) - (int)blockIdx.x;   // heavy first
    const int bh = blockIdx.y;
    const int q0 = qt * 128;
    const int wq = wid * 16;
    const size_t base = (size_t)bh * SEQ * DH;

    // Load Q tile (128 x 64) as tf32
#pragma unroll
    for (int it = 0; it < 8; it++) {
        const int id = it * 256 + tid;
        const int row = id >> 4, f4 = (id & 15) << 2;
        float4 v = *(const float4*)&g_Q[base + (size_t)(q0 + row) * DH + f4];
        uint4 t = make_uint4(f2tf32(v.x), f2tf32(v.y), f2tf32(v.z), f2tf32(v.w));
        *(uint4*)&Qs[row * AST + f4] = t;
    }

    float o[8][4];
#pragma unroll
    for (int nf = 0; nf < 8; nf++)
#pragma unroll
        for (int e = 0; e < 4; e++) o[nf][e] = 0.0f;
    float m0v = -1e30f, m1v = -1e30f, l0v = 0.0f, l1v = 0.0f;

    const int vc = tid & 63;        // V^T loader column
    const int vdg = (tid >> 6) << 4;

    const int ntiles = 2 * qt + 2;
    for (int t = 0; t < ntiles; t++) {
        const int k0g = t * 64;
        __syncthreads();
        // K tile -> Ks[c][d] tf32
#pragma unroll
        for (int it = 0; it < 4; it++) {
            const int id = it * 256 + tid;
            const int c = id >> 4, f4 = (id & 15) << 2;
            float4 v = *(const float4*)&g_K[base + (size_t)(k0g + c) * DH + f4];
            uint4 tt = make_uint4(f2tf32(v.x), f2tf32(v.y), f2tf32(v.z), f2tf32(v.w));
            *(uint4*)&Ks[c * AST + f4] = tt;
        }
        // V tile transposed -> Vs[d][c] tf32
#pragma unroll
        for (int i = 0; i < 4; i++) {
            float4 v = *(const float4*)&g_V[base + (size_t)(k0g + vc) * DH + vdg + i * 4];
            Vs[(vdg + i * 4 + 0) * AST + vc] = f2tf32(v.x);
            Vs[(vdg + i * 4 + 1) * AST + vc] = f2tf32(v.y);
            Vs[(vdg + i * 4 + 2) * AST + vc] = f2tf32(v.z);
            Vs[(vdg + i * 4 + 3) * AST + vc] = f2tf32(v.w);
        }
        __syncthreads();

        // Scores: S[16 x 64] per warp = Q(16xk) . K(64xk)^T
        float sfr[8][4];
#pragma unroll
        for (int nf = 0; nf < 8; nf++)
#pragma unroll
            for (int e = 0; e < 4; e++) sfr[nf][e] = 0.0f;
#pragma unroll
        for (int k = 0; k < 8; k++) {
            const int k0 = k * 8;
            const uint32_t* qb = Qs + (wq + r) * AST + k0 + cl;
            uint32_t af[4] = {qb[0], qb[8 * AST], qb[4], qb[8 * AST + 4]};
#pragma unroll
            for (int nf = 0; nf < 8; nf++) {
                const uint32_t* kb = Ks + (nf * 8 + r) * AST + k0 + cl;
                MMA_TF32(sfr[nf], af, kb[0], kb[4]);
            }
        }

        // Causal mask (only the 2 diagonal-overlap tiles)
        if (t >= 2 * qt) {
            const int row0 = q0 + wq + r, row1 = row0 + 8;
#pragma unroll
            for (int nf = 0; nf < 8; nf++) {
                const int c0 = k0g + nf * 8 + 2 * cl;
                if (c0 > row0) sfr[nf][0] = -1e30f;
                if (c0 + 1 > row0) sfr[nf][1] = -1e30f;
                if (c0 > row1) sfr[nf][2] = -1e30f;
                if (c0 + 1 > row1) sfr[nf][3] = -1e30f;
            }
        }

        // Online softmax (rows r and r+8 of this warp's 16)
        float mx0 = -1e30f, mx1 = -1e30f;
#pragma unroll
        for (int nf = 0; nf < 8; nf++) {
            mx0 = fmaxf(mx0, fmaxf(sfr[nf][0], sfr[nf][1]));
            mx1 = fmaxf(mx1, fmaxf(sfr[nf][2], sfr[nf][3]));
        }
        mx0 = fmaxf(mx0, __shfl_xor_sync(0xffffffffu, mx0, 1));
        mx0 = fmaxf(mx0, __shfl_xor_sync(0xffffffffu, mx0, 2));
        mx1 = fmaxf(mx1, __shfl_xor_sync(0xffffffffu, mx1, 1));
        mx1 = fmaxf(mx1, __shfl_xor_sync(0xffffffffu, mx1, 2));
        const float mn0 = fmaxf(m0v, mx0), mn1 = fmaxf(m1v, mx1);
        const float a0 = __expf(m0v - mn0), a1 = __expf(m1v - mn1);
        float rs0 = 0.0f, rs1 = 0.0f;
        uint32_t* pb0 = Ps + (wq + r) * AST + 2 * cl;
        uint32_t* pb1 = pb0 + 8 * AST;
#pragma unroll
        for (int nf = 0; nf < 8; nf++) {
            const float p0 = __expf(sfr[nf][0] - mn0);
            const float p1 = __expf(sfr[nf][1] - mn0);
            const float p2 = __expf(sfr[nf][2] - mn1);
            const float p3 = __expf(sfr[nf][3] - mn1);
            rs0 += p0 + p1;
            rs1 += p2 + p3;
            pb0[nf * 8 + 0] = f2tf32(p0);
            pb0[nf * 8 + 1] = f2tf32(p1);
            pb1[nf * 8 + 0] = f2tf32(p2);
            pb1[nf * 8 + 1] = f2tf32(p3);
        }
        rs0 += __shfl_xor_sync(0xffffffffu, rs0, 1);
        rs0 += __shfl_xor_sync(0xffffffffu, rs0, 2);
        rs1 += __shfl_xor_sync(0xffffffffu, rs1, 1);
        rs1 += __shfl_xor_sync(0xffffffffu, rs1, 2);
        l0v = l0v * a0 + rs0;
        l1v = l1v * a1 + rs1;
        m0v = mn0;
        m1v = mn1;
#pragma unroll
        for (int nf = 0; nf < 8; nf++) {
            o[nf][0] *= a0;
            o[nf][1] *= a0;
            o[nf][2] *= a1;
            o[nf][3] *= a1;
        }
        __syncwarp();   // P rows are warp-private; make them visible in-warp

        // O += P(16x64) . V(64x64)  via Vt b-frags
#pragma unroll
        for (int k = 0; k < 8; k++) {
            const int k0 = k * 8;
            const uint32_t* pb = Ps + (wq + r) * AST + k0 + cl;
            uint32_t af[4] = {pb[0], pb[8 * AST], pb[4], pb[8 * AST + 4]};
#pragma unroll
            for (int nf = 0; nf < 8; nf++) {
                const uint32_t* vb = Vs + (nf * 8 + r) * AST + k0 + cl;
                MMA_TF32(o[nf], af, vb[0], vb[4]);
            }
        }
    }

    // Epilogue: normalize and write g_O [B,S,D]
    const float i0 = 1.0f / l0v, i1 = 1.0f / l1v;
    const int b = bh >> 4, h = bh & 15;
    const int row0 = q0 + wq + r, row1 = row0 + 8;
#pragma unroll
    for (int nf = 0; nf < 8; nf++) {
        const int col = h * DH + nf * 8 + 2 * cl;
        *(float2*)&g_O[(size_t)(b * SEQ + row0) * DM + col] =
            make_float2(o[nf][0] * i0, o[nf][1] * i0);
        *(float2*)&g_O[(size_t)(b * SEQ + row1) * DM + col] =
            make_float2(o[nf][2] * i1, o[nf][3] * i1);
    }
}

// ============================================================================
// Launch
// ============================================================================
extern "C" void kernel_launch(void* const* d_in, const int* in_sizes, int n_in,
                              void* d_out, int out_size) {
    const float* q  = (const float*)d_in[0];
    const float* kv = (const float*)d_in[1];
    const float* Wq = (const float*)d_in[2];
    const float* Wk = (const float*)d_in[3];
    const float* Wv = (const float*)d_in[4];
    const float* Wo = (const float*)d_in[5];
    float* out = (float*)d_out;

    cudaFuncSetAttribute(attn_mma, cudaFuncAttributeMaxDynamicSharedMemorySize,
                         ATTN_SMEM_BYTES);

    qkv_gemm_mma<<<dim3(DM / 128, (BATCH * SEQ) / 128, 3), 256>>>(q, kv, Wq, Wk, Wv);
    attn_mma<<<dim3(SEQ / 128, BATCH * NH), 256, ATTN_SMEM_BYTES>>>();
    proj_gemm_mma<<<dim3(DM / 128, (BATCH * SEQ) / 128), 256>>>(Wo, out);
}

// round 5
// speedup vs baseline: 2.8815x; 1.1321x over previous
#include <cuda_runtime.h>
#include <cstdint>

#define DM   1024
#define SEQ  2048
#define BATCH 4
#define NH   16
#define DH   64

// Scratch (allocation-free)
__device__ float g_Q[BATCH * NH * SEQ * DH];   // [B,H,S,Dh], pre-scaled by Dh^-0.5
__device__ float g_K[BATCH * NH * SEQ * DH];
__device__ float g_V[BATCH * NH * SEQ * DH];
__device__ float g_O[BATCH * SEQ * DM];        // [B,S,D]

// ============================================================================
// Helpers
// ============================================================================
__device__ __forceinline__ uint32_t f2tf32(float x) {
    uint32_t u;
    asm("cvt.rna.tf32.f32 %0, %1;" : "=r"(u) : "f"(x));
    return u;
}
__device__ __forceinline__ uint32_t smem_u32(const void* p) {
    uint32_t a;
    asm("{ .reg .u64 t; cvta.to.shared.u64 t, %1; cvt.u32.u64 %0, t; }" : "=r"(a) : "l"(p));
    return a;
}

#define MMA_TF32(d, a, b0v, b1v)                                               \
    asm volatile("mma.sync.aligned.m16n8k8.row.col.f32.tf32.tf32.f32 "         \
                 "{%0,%1,%2,%3}, {%4,%5,%6,%7}, {%8,%9}, {%0,%1,%2,%3};"       \
                 : "+f"((d)[0]), "+f"((d)[1]), "+f"((d)[2]), "+f"((d)[3])      \
                 : "r"((a)[0]), "r"((a)[1]), "r"((a)[2]), "r"((a)[3]),         \
                   "r"(b0v), "r"(b1v))

#define LDSM_X4(d, addr)                                                       \
    asm volatile("ldmatrix.sync.aligned.m8n8.x4.shared.b16 {%0,%1,%2,%3}, [%4];" \
                 : "=r"((d)[0]), "=r"((d)[1]), "=r"((d)[2]), "=r"((d)[3])      \
                 : "r"(addr))

#define SST 20

// ============================================================================
// GEMM mainloop: CTA 128x128, 4 warps (128 thr), warp tile 64x64 (mt=4,nt=8).
// Fragment loads via ldmatrix.x4 (tf32-as-b16 trick). Double-buffered smem.
// ============================================================================
__device__ __forceinline__ void gemm_mainloop_64(const float* __restrict__ Ablk,
                                                 const float* __restrict__ Wblk,
                                                 uint32_t (*As)[2560],
                                                 uint32_t (*Ws)[2560],
                                                 float (*acc)[8][4],
                                                 int tid) {
    const int lane = tid & 31;
    const int wid = tid >> 5;
    const int wm = (wid & 1) << 6;
    const int wn = (wid >> 1) << 6;
    const int mat = lane >> 3, lrow = lane & 7;
    // ldmatrix per-thread row/col constants
    const int a_row = wm + ((mat & 1) << 3) + lrow;   // + mt*16, a-matrix order: r, r+8, col+4 pair
    const int a_col = (mat >> 1) << 2;                // + k0
    const int b_row = wn + ((mat >> 1) << 3) + lrow;  // + pair*16
    const int b_col = (mat & 1) << 2;                 // + k0
    const uint32_t As_b = smem_u32(As);
    const uint32_t Ws_b = smem_u32(Ws);

#pragma unroll
    for (int mt = 0; mt < 4; mt++)
#pragma unroll
        for (int nt = 0; nt < 8; nt++)
#pragma unroll
            for (int e = 0; e < 4; e++) acc[mt][nt][e] = 0.0f;

    // prologue: chunk 0
#pragma unroll
    for (int it = 0; it < 4; it++) {
        const int id = it * 128 + tid;
        const int row = id >> 2, f4 = id & 3;
        float4 va = *(const float4*)(Ablk + (size_t)row * DM + f4 * 4);
        float4 vw = *(const float4*)(Wblk + (size_t)row * DM + f4 * 4);
        uint4 ta = make_uint4(f2tf32(va.x), f2tf32(va.y), f2tf32(va.z), f2tf32(va.w));
        uint4 tw = make_uint4(f2tf32(vw.x), f2tf32(vw.y), f2tf32(vw.z), f2tf32(vw.w));
        *(uint4*)(&As[0][row * SST + f4 * 4]) = ta;
        *(uint4*)(&Ws[0][row * SST + f4 * 4]) = tw;
    }
    __syncthreads();

    float4 ra[4], rw[4];
#pragma unroll 1
    for (int c = 0; c < 64; c++) {
        const int cur = c & 1;
        if (c + 1 < 64) {
#pragma unroll
            for (int it = 0; it < 4; it++) {
                const int id = it * 128 + tid;
                const int row = id >> 2, f4 = id & 3;
                ra[it] = *(const float4*)(Ablk + (size_t)row * DM + (c + 1) * 16 + f4 * 4);
                rw[it] = *(const float4*)(Wblk + (size_t)row * DM + (c + 1) * 16 + f4 * 4);
            }
        }
        const uint32_t asb = As_b + (uint32_t)cur * (2560 * 4);
        const uint32_t wsb = Ws_b + (uint32_t)cur * (2560 * 4);
#pragma unroll
        for (int k0 = 0; k0 < 16; k0 += 8) {
            uint32_t af[4][4], bf[4][4];
#pragma unroll
            for (int mt = 0; mt < 4; mt++)
                LDSM_X4(af[mt], asb + (uint32_t)(((a_row + mt * 16) * SST + k0 + a_col) * 4));
#pragma unroll
            for (int p = 0; p < 4; p++)
                LDSM_X4(bf[p], wsb + (uint32_t)(((b_row + p * 16) * SST + k0 + b_col) * 4));
#pragma unroll
            for (int nt = 0; nt < 8; nt++) {
                const uint32_t b0 = bf[nt >> 1][(nt & 1) << 1];
                const uint32_t b1 = bf[nt >> 1][((nt & 1) << 1) + 1];
#pragma unroll
                for (int mt = 0; mt < 4; mt++)
                    MMA_TF32(acc[mt][nt], af[mt], b0, b1);
            }
        }
        if (c + 1 < 64) {
            const int nxt = cur ^ 1;
#pragma unroll
            for (int it = 0; it < 4; it++) {
                const int id = it * 128 + tid;
                const int row = id >> 2, f4 = id & 3;
                uint4 ta = make_uint4(f2tf32(ra[it].x), f2tf32(ra[it].y),
                                      f2tf32(ra[it].z), f2tf32(ra[it].w));
                uint4 tw = make_uint4(f2tf32(rw[it].x), f2tf32(rw[it].y),
                                      f2tf32(rw[it].z), f2tf32(rw[it].w));
                *(uint4*)(&As[nxt][row * SST + f4 * 4]) = ta;
                *(uint4*)(&Ws[nxt][row * SST + f4 * 4]) = tw;
            }
            __syncthreads();
        }
    }
}

__global__ void __launch_bounds__(128) qkv_gemm_mma(const float* __restrict__ Xq,
                                                    const float* __restrict__ Xkv,
                                                    const float* __restrict__ Wq,
                                                    const float* __restrict__ Wk,
                                                    const float* __restrict__ Wv) {
    __shared__ uint32_t As[2][2560];
    __shared__ uint32_t Ws[2][2560];
    const int bz = blockIdx.z;
    const float* A = (bz == 0) ? Xq : Xkv;
    const float* W = (bz == 0) ? Wq : ((bz == 1) ? Wk : Wv);
    float* out     = (bz == 0) ? g_Q : ((bz == 1) ? g_K : g_V);
    const float scale = (bz == 0) ? 0.125f : 1.0f;

    const int m0 = blockIdx.y * 128;
    const int n0 = blockIdx.x * 128;
    const int tid = threadIdx.x;
    const int lane = tid & 31, wid = tid >> 5;
    const int wm = (wid & 1) << 6, wn = (wid >> 1) << 6;
    const int r = lane >> 2, cl = lane & 3;

    float acc[4][8][4];
    gemm_mainloop_64(A + (size_t)m0 * DM, W + (size_t)n0 * DM, As, Ws, acc, tid);

#pragma unroll
    for (int mt = 0; mt < 4; mt++) {
#pragma unroll
        for (int nt = 0; nt < 8; nt++) {
            const int mr = m0 + wm + mt * 16 + r;
            const int nc = n0 + wn + nt * 8 + 2 * cl;
            const int b = mr >> 11, s = mr & 2047;
            const int h = nc >> 6, dh = nc & 63;
            float* p0 = out + (((size_t)(b * NH + h) * SEQ + s) * DH + dh);
            *(float2*)p0 = make_float2(acc[mt][nt][0] * scale, acc[mt][nt][1] * scale);
            float* p1 = out + (((size_t)(b * NH + h) * SEQ + (s + 8)) * DH + dh);
            *(float2*)p1 = make_float2(acc[mt][nt][2] * scale, acc[mt][nt][3] * scale);
        }
    }
}

__global__ void __launch_bounds__(128) proj_gemm_mma(const float* __restrict__ Wo,
                                                     float* __restrict__ C) {
    __shared__ uint32_t As[2][2560];
    __shared__ uint32_t Ws[2][2560];
    const int m0 = blockIdx.y * 128;
    const int n0 = blockIdx.x * 128;
    const int tid = threadIdx.x;
    const int lane = tid & 31, wid = tid >> 5;
    const int wm = (wid & 1) << 6, wn = (wid >> 1) << 6;
    const int r = lane >> 2, cl = lane & 3;

    float acc[4][8][4];
    gemm_mainloop_64(g_O + (size_t)m0 * DM, Wo + (size_t)n0 * DM, As, Ws, acc, tid);

#pragma unroll
    for (int mt = 0; mt < 4; mt++) {
#pragma unroll
        for (int nt = 0; nt < 8; nt++) {
            const int mr = m0 + wm + mt * 16 + r;
            const int nc = n0 + wn + nt * 8 + 2 * cl;
            *(float2*)&C[(size_t)mr * DM + nc] = make_float2(acc[mt][nt][0], acc[mt][nt][1]);
            *(float2*)&C[(size_t)(mr + 8) * DM + nc] = make_float2(acc[mt][nt][2], acc[mt][nt][3]);
        }
    }
}

// ============================================================================
// Flash attention with tf32 mma.sync + ldmatrix fragments.
// BQ=128, BK=64, Dh=64, 256 threads (8 warps x 16 q-rows each).
// ============================================================================
#define AST 68
#define OFF_Q 0
#define OFF_K (128 * AST)
#define OFF_V (192 * AST)
#define OFF_P (256 * AST)
#define ATTN_SMEM_BYTES (384 * AST * 4)

__global__ void __launch_bounds__(256) attn_mma() {
    extern __shared__ uint32_t sm4[];
    uint32_t* Qs = sm4 + OFF_Q;
    uint32_t* Ks = sm4 + OFF_K;
    uint32_t* Vs = sm4 + OFF_V;
    uint32_t* Ps = sm4 + OFF_P;

    const int tid = threadIdx.x;
    const int wid = tid >> 5, lane = tid & 31;
    const int r = lane >> 2, cl = lane & 3;
    const int mat = lane >> 3, lrow = lane & 7;
    const int qt = (int)(gridDim.x - 1) - (int)blockIdx.x;   // heavy first
    const int bh = blockIdx.y;
    const int q0 = qt * 128;
    const int wq = wid * 16;
    const size_t base = (size_t)bh * SEQ * DH;

    const uint32_t Qs_b = smem_u32(Qs), Ks_b = smem_u32(Ks);
    const uint32_t Vs_b = smem_u32(Vs), Ps_b = smem_u32(Ps);
    // ldmatrix constants
    const int a_off = ((mat & 1) << 3) + lrow;   // row offset within 16-row a-tile
    const int a_col = (mat >> 1) << 2;
    const int b_off = ((mat >> 1) << 3) + lrow;  // row offset within 16-row b-pair
    const int b_col = (mat & 1) << 2;

    // Load Q tile (128 x 64) as tf32
#pragma unroll
    for (int it = 0; it < 8; it++) {
        const int id = it * 256 + tid;
        const int row = id >> 4, f4 = (id & 15) << 2;
        float4 v = *(const float4*)&g_Q[base + (size_t)(q0 + row) * DH + f4];
        uint4 t = make_uint4(f2tf32(v.x), f2tf32(v.y), f2tf32(v.z), f2tf32(v.w));
        *(uint4*)&Qs[row * AST + f4] = t;
    }

    float o[8][4];
#pragma unroll
    for (int nf = 0; nf < 8; nf++)
#pragma unroll
        for (int e = 0; e < 4; e++) o[nf][e] = 0.0f;
    float m0v = -1e30f, m1v = -1e30f, l0v = 0.0f, l1v = 0.0f;

    const int vc = tid & 63;
    const int vdg = (tid >> 6) << 4;

    const int ntiles = 2 * qt + 2;
    for (int t = 0; t < ntiles; t++) {
        const int k0g = t * 64;
        __syncthreads();
#pragma unroll
        for (int it = 0; it < 4; it++) {
            const int id = it * 256 + tid;
            const int c = id >> 4, f4 = (id & 15) << 2;
            float4 v = *(const float4*)&g_K[base + (size_t)(k0g + c) * DH + f4];
            uint4 tt = make_uint4(f2tf32(v.x), f2tf32(v.y), f2tf32(v.z), f2tf32(v.w));
            *(uint4*)&Ks[c * AST + f4] = tt;
        }
#pragma unroll
        for (int i = 0; i < 4; i++) {
            float4 v = *(const float4*)&g_V[base + (size_t)(k0g + vc) * DH + vdg + i * 4];
            Vs[(vdg + i * 4 + 0) * AST + vc] = f2tf32(v.x);
            Vs[(vdg + i * 4 + 1) * AST + vc] = f2tf32(v.y);
            Vs[(vdg + i * 4 + 2) * AST + vc] = f2tf32(v.z);
            Vs[(vdg + i * 4 + 3) * AST + vc] = f2tf32(v.w);
        }
        __syncthreads();

        // Scores: S[16 x 64] per warp
        float sfr[8][4];
#pragma unroll
        for (int nf = 0; nf < 8; nf++)
#pragma unroll
            for (int e = 0; e < 4; e++) sfr[nf][e] = 0.0f;
#pragma unroll
        for (int k = 0; k < 8; k++) {
            const int k0 = k * 8;
            uint32_t af[4], bf[4][4];
            LDSM_X4(af, Qs_b + (uint32_t)(((wq + a_off) * AST + k0 + a_col) * 4));
#pragma unroll
            for (int p = 0; p < 4; p++)
                LDSM_X4(bf[p], Ks_b + (uint32_t)(((p * 16 + b_off) * AST + k0 + b_col) * 4));
#pragma unroll
            for (int nf = 0; nf < 8; nf++)
                MMA_TF32(sfr[nf], af, bf[nf >> 1][(nf & 1) << 1], bf[nf >> 1][((nf & 1) << 1) + 1]);
        }

        // Causal mask (only diagonal-overlap tiles)
        if (t >= 2 * qt) {
            const int row0 = q0 + wq + r, row1 = row0 + 8;
#pragma unroll
            for (int nf = 0; nf < 8; nf++) {
                const int c0 = k0g + nf * 8 + 2 * cl;
                if (c0 > row0) sfr[nf][0] = -1e30f;
                if (c0 + 1 > row0) sfr[nf][1] = -1e30f;
                if (c0 > row1) sfr[nf][2] = -1e30f;
                if (c0 + 1 > row1) sfr[nf][3] = -1e30f;
            }
        }

        // Online softmax
        float mx0 = -1e30f, mx1 = -1e30f;
#pragma unroll
        for (int nf = 0; nf < 8; nf++) {
            mx0 = fmaxf(mx0, fmaxf(sfr[nf][0], sfr[nf][1]));
            mx1 = fmaxf(mx1, fmaxf(sfr[nf][2], sfr[nf][3]));
        }
        mx0 = fmaxf(mx0, __shfl_xor_sync(0xffffffffu, mx0, 1));
        mx0 = fmaxf(mx0, __shfl_xor_sync(0xffffffffu, mx0, 2));
        mx1 = fmaxf(mx1, __shfl_xor_sync(0xffffffffu, mx1, 1));
        mx1 = fmaxf(mx1, __shfl_xor_sync(0xffffffffu, mx1, 2));
        const float mn0 = fmaxf(m0v, mx0), mn1 = fmaxf(m1v, mx1);
        const float a0 = __expf(m0v - mn0), a1 = __expf(m1v - mn1);
        float rs0 = 0.0f, rs1 = 0.0f;
        uint32_t* pb0 = Ps + (wq + r) * AST + 2 * cl;
        uint32_t* pb1 = pb0 + 8 * AST;
#pragma unroll
        for (int nf = 0; nf < 8; nf++) {
            const float p0 = __expf(sfr[nf][0] - mn0);
            const float p1 = __expf(sfr[nf][1] - mn0);
            const float p2 = __expf(sfr[nf][2] - mn1);
            const float p3 = __expf(sfr[nf][3] - mn1);
            rs0 += p0 + p1;
            rs1 += p2 + p3;
            pb0[nf * 8 + 0] = f2tf32(p0);
            pb0[nf * 8 + 1] = f2tf32(p1);
            pb1[nf * 8 + 0] = f2tf32(p2);
            pb1[nf * 8 + 1] = f2tf32(p3);
        }
        rs0 += __shfl_xor_sync(0xffffffffu, rs0, 1);
        rs0 += __shfl_xor_sync(0xffffffffu, rs0, 2);
        rs1 += __shfl_xor_sync(0xffffffffu, rs1, 1);
        rs1 += __shfl_xor_sync(0xffffffffu, rs1, 2);
        l0v = l0v * a0 + rs0;
        l1v = l1v * a1 + rs1;
        m0v = mn0;
        m1v = mn1;
#pragma unroll
        for (int nf = 0; nf < 8; nf++) {
            o[nf][0] *= a0;
            o[nf][1] *= a0;
            o[nf][2] *= a1;
            o[nf][3] *= a1;
        }
        __syncwarp();

        // O += P(16x64) . V(64x64)
#pragma unroll
        for (int k = 0; k < 8; k++) {
            const int k0 = k * 8;
            uint32_t af[4], bf[4][4];
            LDSM_X4(af, Ps_b + (uint32_t)(((wq + a_off) * AST + k0 + a_col) * 4));
#pragma unroll
            for (int p = 0; p < 4; p++)
                LDSM_X4(bf[p], Vs_b + (uint32_t)(((p * 16 + b_off) * AST + k0 + b_col) * 4));
#pragma unroll
            for (int nf = 0; nf < 8; nf++)
                MMA_TF32(o[nf], af, bf[nf >> 1][(nf & 1) << 1], bf[nf >> 1][((nf & 1) << 1) + 1]);
        }
    }

    // Epilogue
    const float i0 = 1.0f / l0v, i1 = 1.0f / l1v;
    const int b = bh >> 4, h = bh & 15;
    const int row0 = q0 + wq + r, row1 = row0 + 8;
#pragma unroll
    for (int nf = 0; nf < 8; nf++) {
        const int col = h * DH + nf * 8 + 2 * cl;
        *(float2*)&g_O[(size_t)(b * SEQ + row0) * DM + col] =
            make_float2(o[nf][0] * i0, o[nf][1] * i0);
        *(float2*)&g_O[(size_t)(b * SEQ + row1) * DM + col] =
            make_float2(o[nf][2] * i1, o[nf][3] * i1);
    }
}

// ============================================================================
// Launch
// ============================================================================
extern "C" void kernel_launch(void* const* d_in, const int* in_sizes, int n_in,
                              void* d_out, int out_size) {
    const float* q  = (const float*)d_in[0];
    const float* kv = (const float*)d_in[1];
    const float* Wq = (const float*)d_in[2];
    const float* Wk = (const float*)d_in[3];
    const float* Wv = (const float*)d_in[4];
    const float* Wo = (const float*)d_in[5];
    float* out = (float*)d_out;

    cudaFuncSetAttribute(attn_mma, cudaFuncAttributeMaxDynamicSharedMemorySize,
                         ATTN_SMEM_BYTES);

    qkv_gemm_mma<<<dim3(DM / 128, (BATCH * SEQ) / 128, 3), 128>>>(q, kv, Wq, Wk, Wv);
    attn_mma<<<dim3(SEQ / 128, BATCH * NH), 256, ATTN_SMEM_BYTES>>>();
    proj_gemm_mma<<<dim3(DM / 128, (BATCH * SEQ) / 128), 128>>>(Wo, out);
}